// round 11
// baseline (speedup 1.0000x reference)
#include <cuda_runtime.h>

#define BS      16
#define NANCH   33600
#define NV4     8400
#define NCH     56
#define KTOP    3000
#define CAP     4096
#define NB      4096
#define MAXDET  300
#define CONF_T  0.25f
#define IOU_T   0.7f
#define IMGW    1280.0f
#define FULLM   0xFFFFFFFFu
#define BPI     8
#define CHUNK   1050
#define STILE   128
#define LCAP    432

// ---------------- global scratch (L2-resident) ----------------
__device__ unsigned           g_hist  [BS * NB];   // zeroed by K2 main part each run
__device__ unsigned           g_bstart[BS * NB];
__device__ unsigned           g_cursor[BS * NB];
__device__ int                g_cutoff[BS];
__device__ unsigned long long g_keys  [BS * CAP];
__device__ unsigned           g_done1 [BS];        // ticket, self-resetting
__device__ unsigned           g_done2 [BS];        // ticket, self-resetting
__device__ int                g_cnt   [BS];
__device__ float4             g_selbox  [BS * MAXDET];
__device__ float              g_selscore[BS * MAXDET];
__device__ int                g_selanch [BS * MAXDET];

__device__ __forceinline__ unsigned ordkey(float f) {
    unsigned b = __float_as_uint(f);
    return (b & 0x80000000u) ? ~b : (b | 0x80000000u);
}
__device__ __forceinline__ float inv_ordkey(unsigned u) {
    unsigned bits = (u & 0x80000000u) ? (u & 0x7FFFFFFFu) : ~u;
    return __uint_as_float(bits);
}
__device__ __forceinline__ int bucket_of(float s) {
    int b = (int)(s * 4096.0f);
    return min(4095, max(0, b));
}
// suppression test, bit-identical to reference rounding (rel_err=0 R1..R10)
__device__ __forceinline__ bool sup_test(float ax, float ay, float az, float aw, float aa,
                                         float bx, float by, float bz, float bw, float ab) {
    float xx1 = fmaxf(ax, bx);
    float yy1 = fmaxf(ay, by);
    float xx2 = fminf(az, bz);
    float yy2 = fminf(aw, bw);
    float ww  = fmaxf(xx2 - xx1, 0.0f);
    float hh  = fmaxf(yy2 - yy1, 0.0f);
    float inter = __fmul_rn(ww, hh);
    if (inter <= 0.0f) return false;
    float denom = __fadd_rn(__fsub_rn(__fadd_rn(aa, ab), inter), 1e-9f);
    return (inter / denom) > IOU_T;
}

// ---------------- K1: histogram; LAST block per image does the scan ----------------
__global__ void __launch_bounds__(1024) k_hist(const float* __restrict__ preds) {
    __shared__ unsigned wsum[32];
    __shared__ int sb, slast;
    const int img  = blockIdx.x >> 3;
    const int part = blockIdx.x & 7;
    const int tid  = threadIdx.x;
    const int lane = tid & 31;
    const int wid  = tid >> 5;
    const float4* conf4 = (const float4*)(preds + (size_t)img * NCH * NANCH + 4 * (size_t)NANCH);
    unsigned* hist = g_hist + img * NB;
    const int st = part * CHUNK;
    const int en = min(NV4, st + CHUNK);

    for (int i = st + tid; i < en; i += 1024) {
        float4 v = conf4[i];
        if (v.x > CONF_T) atomicAdd(&hist[bucket_of(v.x)], 1u);
        if (v.y > CONF_T) atomicAdd(&hist[bucket_of(v.y)], 1u);
        if (v.z > CONF_T) atomicAdd(&hist[bucket_of(v.z)], 1u);
        if (v.w > CONF_T) atomicAdd(&hist[bucket_of(v.w)], 1u);
    }
    __syncthreads();
    if (tid == 0) {
        __threadfence();                                   // release hist atomics
        slast = (atomicAdd(&g_done1[img], 1u) == BPI - 1);
        sb = 0;
    }
    __syncthreads();
    if (!slast) return;

    // ---- last block: acquire + scan ----
    __threadfence();
    if (tid == 0) g_done1[img] = 0u;                       // reset ticket for next replay

    uint4 hv = ((const uint4*)hist)[tid];
    unsigned tot = hv.x + hv.y + hv.z + hv.w;
    unsigned suf = tot;
    #pragma unroll
    for (int d = 1; d < 32; d <<= 1) {
        unsigned v = __shfl_down_sync(FULLM, suf, d);
        if (lane + d < 32) suf += v;
    }
    if (lane == 0) wsum[wid] = suf;
    __syncthreads();
    if (tid < 32) {
        unsigned v  = wsum[tid];
        unsigned sv = v;
        #pragma unroll
        for (int d = 1; d < 32; d <<= 1) {
            unsigned u = __shfl_down_sync(FULLM, sv, d);
            if (tid + d < 32) sv += u;
        }
        wsum[tid] = sv - v;
    }
    __syncthreads();
    unsigned run = wsum[wid] + (suf - tot);
    unsigned e3 = run;
    unsigned e2 = e3 + hv.w;
    unsigned e1 = e2 + hv.z;
    unsigned e0 = e1 + hv.y;
    uint4 ev = make_uint4(e0, e1, e2, e3);
    ((uint4*)(g_bstart + img * NB))[tid] = ev;
    ((uint4*)(g_cursor + img * NB))[tid] = ev;
    if      (e3 + hv.w >= (unsigned)KTOP) atomicMax(&sb, 4 * tid + 3);
    else if (e2 + hv.z >= (unsigned)KTOP) atomicMax(&sb, 4 * tid + 2);
    else if (e1 + hv.y >= (unsigned)KTOP) atomicMax(&sb, 4 * tid + 1);
    else if (e0 + hv.x >= (unsigned)KTOP) atomicMax(&sb, 4 * tid + 0);
    __syncthreads();
    if (tid == 0) g_cutoff[img] = sb;
}

// ---------------- K2: scatter; LAST block per image runs rank + NMS + emit ----------------
// smem layout (bytes)
#define OFF_EN     0                      // 4096*4
#define OFF_BST    16384                  // 4096*4
#define OFF_KEYS   32768                  // 4096*8
#define OFF_KEYS2  65536                  // 4096*8
#define OFF_LBOX   98304                  // 432*16
#define OFF_LAREA  (OFF_LBOX  + 6912)
#define OFF_LKEY   (OFF_LAREA + 1728)     // 304*8
#define OFF_TBOX   (OFF_LKEY  + 2432)     // 2*128*16
#define OFF_TAREA  (OFF_TBOX  + 4096)     // 2*128*4
#define OFF_SMAT   (OFF_TAREA + 1024)     // 128*4*4
#define OFF_SSUPW  (OFF_SMAT  + 2048)     // 32*4
#define SMEM_TOTAL (OFF_SSUPW + 128)

__device__ __forceinline__ void decode_box(const float* pimg, unsigned long long key,
                                           float4& b, float& area) {
    int anchor = 65535 - (int)(key & 0xFFFFull);
    anchor = min(anchor, NANCH - 1);
    float cx = pimg[anchor];
    float cy = pimg[(size_t)NANCH + anchor];
    float w  = pimg[2 * (size_t)NANCH + anchor];
    float ht = pimg[3 * (size_t)NANCH + anchor];
    float hw = w * 0.5f, hh = ht * 0.5f;
    b.x = fminf(fmaxf(cx - hw, 0.0f), IMGW);
    b.y = fminf(fmaxf(cy - hh, 0.0f), IMGW);
    b.z = fminf(fmaxf(cx + hw, 0.0f), IMGW);
    b.w = fminf(fmaxf(cy + hh, 0.0f), IMGW);
    area = __fmul_rn(b.z - b.x, b.w - b.y);
}

__global__ void __launch_bounds__(1024) k_scatmain(const float* __restrict__ preds) {
    extern __shared__ char sm[];
    __shared__ int s_count, s_stop, slast;
    const int img  = blockIdx.x >> 3;
    const int part = blockIdx.x & 7;
    const int tid  = threadIdx.x;
    const int lane = tid & 31;
    const int wrp  = tid >> 5;
    const float* pimg  = preds + (size_t)img * NCH * NANCH;
    const float4* conf4 = (const float4*)(pimg + 4 * (size_t)NANCH);

    // ---- scatter phase (all 8 blocks) ----
    {
        const int cutoff = g_cutoff[img];
        unsigned* cursor = g_cursor + img * NB;
        unsigned long long* keys = g_keys + img * CAP;
        const int st = part * CHUNK;
        const int en = min(NV4, st + CHUNK);
        for (int i = st + tid; i < en; i += 1024) {
            float4 v = conf4[i];
            float sv[4] = {v.x, v.y, v.z, v.w};
            int a = 4 * i;
            #pragma unroll
            for (int c = 0; c < 4; c++) {
                float s = sv[c];
                if (s > CONF_T) {
                    int b = bucket_of(s);
                    if (b >= cutoff) {
                        unsigned pos = atomicAdd(&cursor[b], 1u);
                        if (pos < CAP)
                            keys[pos] = ((unsigned long long)ordkey(s) << 16)
                                      | (unsigned)(65535 - (a + c));
                    }
                }
            }
        }
    }
    __syncthreads();
    if (tid == 0) {
        __threadfence();                                   // release key writes
        slast = (atomicAdd(&g_done2[img], 1u) == BPI - 1);
    }
    __syncthreads();
    if (!slast) return;

    // ---- last block continues: acquire + rank + NMS + emit ----
    __threadfence();
    if (tid == 0) g_done2[img] = 0u;                       // reset ticket

    unsigned*           sen   = (unsigned*)(sm + OFF_EN);
    unsigned*           sbst  = (unsigned*)(sm + OFF_BST);
    unsigned long long* keys  = (unsigned long long*)(sm + OFF_KEYS);
    unsigned long long* keys2 = (unsigned long long*)(sm + OFF_KEYS2);
    float4*             lbox  = (float4*)(sm + OFF_LBOX);
    float*              larea = (float*)(sm + OFF_LAREA);
    unsigned long long* lkey  = (unsigned long long*)(sm + OFF_LKEY);
    float4*             tbox  = (float4*)(sm + OFF_TBOX);
    float*              tarea = (float*)(sm + OFF_TAREA);
    unsigned*           smat  = (unsigned*)(sm + OFF_SMAT);
    unsigned*           ssupw = (unsigned*)(sm + OFF_SSUPW);

    ((uint4*)sen)[tid]  = ((const uint4*)(g_cursor + img * NB))[tid];
    ((uint4*)sbst)[tid] = ((const uint4*)(g_bstart + img * NB))[tid];
    for (int r = tid; r < CAP; r += 1024) {
        keys[r]  = g_keys[img * CAP + r];
        keys2[r] = 0ull;
    }
    if (tid == 0) { s_count = 0; s_stop = 0; }
    __syncthreads();

    // zero g_hist for next graph replay
    for (int i = tid; i < NB; i += 1024) g_hist[img * NB + i] = 0u;

    const int cutoff = g_cutoff[img];
    const int ntot   = min((int)sen[cutoff], CAP);

    // ---- exact within-bucket ranking -> keys2 sorted desc ----
    for (int p = tid; p < ntot; p += 1024) {
        unsigned long long key = keys[p];
        float sc = inv_ordkey((unsigned)(key >> 16));
        int b  = bucket_of(sc);
        int st = (int)sbst[b];
        int en = min((int)sen[b], CAP);
        int rank = st;
        for (int q = st; q < en; q++) rank += (keys[q] > key) ? 1 : 0;
        keys2[rank] = key;
    }
    __syncthreads();

    // ---- preload super-tile 0 ----
    if (tid >= 64 && tid < 192) {
        int c = tid - 64;
        float4 b; float ar;
        decode_box(pimg, keys2[c], b, ar);
        tbox[c] = b; tarea[c] = ar;
    }
    __syncthreads();

    // ---- super-tile NMS loop ----
    int buf = 0;
    for (int base = 0; base < KTOP; base += STILE, buf ^= 1) {
        if (tid >= 64 && tid < 192 && base + STILE < KTOP) {
            int c = tid - 64;
            float4 b; float ar;
            decode_box(pimg, keys2[base + STILE + c], b, ar);
            tbox[(buf ^ 1) * STILE + c] = b;
            tarea[(buf ^ 1) * STILE + c] = ar;
        }
        // A2: leader tests
        {
            const int j  = tid >> 3;
            const int k  = tid & 7;
            const int cj = base + j;
            float sc = inv_ordkey((unsigned)(keys2[min(cj, CAP - 1)] >> 16));
            bool bad = !((cj < KTOP) && (sc > CONF_T));
            if (!bad) {
                float4 bj = tbox[buf * STILE + j];
                float  aj = tarea[buf * STILE + j];
                const int cnt = s_count;
                for (int l = k; l < cnt; l += 8) {
                    float4 bl = lbox[l];
                    bad |= sup_test(bl.x, bl.y, bl.z, bl.w, larea[l],
                                    bj.x, bj.y, bj.z, bj.w, aj);
                }
            }
            unsigned bm = __ballot_sync(FULLM, bad);
            if (lane == 0) ssupw[wrp] = bm;
        }
        // A3: 128x128 suppression bit-matrix
        {
            #pragma unroll
            for (int r = 0; r < 4; r++) {
                const int i = 4 * wrp + r;
                float4 bi = tbox[buf * STILE + i];
                float  ai = tarea[buf * STILE + i];
                #pragma unroll
                for (int cw = 0; cw < 4; cw++) {
                    const int j = cw * 32 + lane;
                    bool bit = false;
                    if (j > i) {
                        float4 bj = tbox[buf * STILE + j];
                        float  aj = tarea[buf * STILE + j];
                        bit = sup_test(bi.x, bi.y, bi.z, bi.w, ai,
                                       bj.x, bj.y, bj.z, bj.w, aj);
                    }
                    unsigned bm = __ballot_sync(FULLM, bit);
                    if (lane == 0) smat[i * 4 + cw] = bm;
                }
            }
        }
        __syncthreads();

        // phase B: warp 0 resolves 128-candidate greedy
        if (tid < 32) {
            unsigned S1 = 0, S2 = 0, S3 = 0;
            int cur = s_count;
            #pragma unroll
            for (int m = 0; m < 4; m++) {
                const int c = 32 * m + lane;
                unsigned supb = (ssupw[8 * m + (lane >> 2)] >> ((lane & 3) * 8)) & 0xFFu;
                unsigned Sm = (m == 1) ? S1 : (m == 2) ? S2 : (m == 3) ? S3 : 0u;
                bool alive = (supb == 0u) && !((Sm >> lane) & 1u);
                unsigned aliveb = __ballot_sync(FULLM, alive);
                unsigned rm = smat[c * 4 + m];
                unsigned kept;
                if (__ballot_sync(FULLM, (rm & aliveb) != 0u) == 0u) {
                    kept = aliveb;
                } else {
                    unsigned Sl = 0; kept = 0;
                    #pragma unroll 4
                    for (int ii = 0; ii < 32; ii++) {
                        unsigned ri = __shfl_sync(FULLM, rm, ii);
                        bool ki = ((aliveb >> ii) & 1u) && !((Sl >> ii) & 1u);
                        if (ki) { kept |= (1u << ii); Sl |= ri; }
                    }
                }
                if ((kept >> lane) & 1u) {
                    int pos = cur + __popc(kept & ((1u << lane) - 1u));
                    if (pos < LCAP) {
                        lbox[pos]  = tbox[buf * STILE + c];
                        larea[pos] = tarea[buf * STILE + c];
                    }
                    if (pos < MAXDET) lkey[pos] = keys2[base + c];
                }
                cur += __popc(kept);
                unsigned kb = (kept >> lane) & 1u;
                if (m < 1) S1 |= __reduce_or_sync(FULLM, kb ? smat[c * 4 + 1] : 0u);
                if (m < 2) S2 |= __reduce_or_sync(FULLM, kb ? smat[c * 4 + 2] : 0u);
                if (m < 3) S3 |= __reduce_or_sync(FULLM, kb ? smat[c * 4 + 3] : 0u);
            }
            if (lane == 0) {
                s_count = cur;
                if (cur >= MAXDET) s_stop = 1;
            }
        }
        __syncthreads();
        if (s_stop) break;
    }
    __syncthreads();

    // ---- emit compact per-image selection ----
    const int cnt = min(s_count, MAXDET);
    if (tid < cnt) {
        unsigned long long key = lkey[tid];
        g_selbox  [img * MAXDET + tid] = lbox[tid];
        g_selscore[img * MAXDET + tid] = inv_ordkey((unsigned)(key >> 16));
        g_selanch [img * MAXDET + tid] = 65535 - (int)(key & 0xFFFFull);
    }
    if (tid == 0) g_cnt[img] = cnt;
}

// ---------------- K3: wide output writer ----------------
#define TOTOUT (BS * MAXDET * 56)
__global__ void __launch_bounds__(1024) k_out(const float* __restrict__ preds,
                                              float* __restrict__ out) {
    int s = blockIdx.x * 1024 + threadIdx.x;
    if (s >= TOTOUT) return;
    const int img = s / (MAXDET * 56);
    const int rem = s % (MAXDET * 56);
    const int r   = rem / 56;
    const int f   = rem % 56;
    const int cnt = g_cnt[img];

    float v = 0.0f;
    if (r < cnt) {
        if (f < 4) {
            float4 b = g_selbox[img * MAXDET + r];
            v = (f == 0) ? b.x : (f == 1) ? b.y : (f == 2) ? b.z : b.w;
        } else if (f == 4) {
            v = g_selscore[img * MAXDET + r];
        } else {
            int c = f - 5;
            int a = g_selanch[img * MAXDET + r];
            v = preds[(size_t)img * NCH * NANCH + (size_t)(5 + c) * NANCH + a];
            if (c < 2) v = fminf(fmaxf(v, 0.0f), IMGW);
        }
    }
    const int OSC = BS * MAXDET * 4;
    const int OKP = OSC + BS * MAXDET;
    if (f < 4)       out[(img * MAXDET + r) * 4 + f] = v;
    else if (f == 4) out[OSC + img * MAXDET + r] = v;
    else             out[OKP + (img * MAXDET + r) * 51 + (f - 5)] = v;
}

// ---------------- launch ----------------
extern "C" void kernel_launch(void* const* d_in, const int* in_sizes, int n_in,
                              void* d_out, int out_size) {
    const float* preds = (const float*)d_in[0];
    float* out = (float*)d_out;
    cudaFuncSetAttribute(k_scatmain, cudaFuncAttributeMaxDynamicSharedMemorySize, SMEM_TOTAL);
    k_hist    <<<BS * BPI, 1024>>>(preds);
    k_scatmain<<<BS * BPI, 1024, SMEM_TOTAL>>>(preds);
    k_out     <<<(TOTOUT + 1023) / 1024, 1024>>>(preds, out);
}

// round 12
// speedup vs baseline: 1.0529x; 1.0529x over previous
#include <cuda_runtime.h>

#define BS      16
#define NANCH   33600
#define NV4     8400
#define NCH     56
#define KTOP    3000
#define CAP     4096
#define NB      4096
#define MAXDET  300
#define CONF_T  0.25f
#define IOU_T   0.7f
#define IMGW    1280.0f
#define FULLM   0xFFFFFFFFu
#define BPI     8
#define CHUNK   1050
#define STILE   128
#define LCAP    432

// ---------------- global scratch (L2-resident) ----------------
__device__ unsigned           g_histp [BS * BPI * NB];  // fully overwritten each run
__device__ unsigned           g_bstart[BS * NB];
__device__ unsigned           g_cursor[BS * NB];
__device__ int                g_cutoff[BS];
__device__ unsigned long long g_keys  [BS * CAP];       // only [bstart,cursor) read
__device__ unsigned           g_done1 [BS];             // ticket, self-resetting
__device__ unsigned           g_done2 [BS];             // ticket, self-resetting
__device__ int                g_cnt   [BS];
__device__ float4             g_selbox  [BS * MAXDET];
__device__ float              g_selscore[BS * MAXDET];
__device__ int                g_selanch [BS * MAXDET];

__device__ __forceinline__ unsigned ordkey(float f) {
    unsigned b = __float_as_uint(f);
    return (b & 0x80000000u) ? ~b : (b | 0x80000000u);
}
__device__ __forceinline__ float inv_ordkey(unsigned u) {
    unsigned bits = (u & 0x80000000u) ? (u & 0x7FFFFFFFu) : ~u;
    return __uint_as_float(bits);
}
__device__ __forceinline__ int bucket_of(float s) {
    int b = (int)(s * 4096.0f);
    return min(4095, max(0, b));
}
// suppression test, bit-identical to reference rounding (rel_err=0 R1..R11)
__device__ __forceinline__ bool sup_test(float ax, float ay, float az, float aw, float aa,
                                         float bx, float by, float bz, float bw, float ab) {
    float xx1 = fmaxf(ax, bx);
    float yy1 = fmaxf(ay, by);
    float xx2 = fminf(az, bz);
    float yy2 = fminf(aw, bw);
    float ww  = fmaxf(xx2 - xx1, 0.0f);
    float hh  = fmaxf(yy2 - yy1, 0.0f);
    float inter = __fmul_rn(ww, hh);
    if (inter <= 0.0f) return false;
    float denom = __fadd_rn(__fsub_rn(__fadd_rn(aa, ab), inter), 1e-9f);
    return (inter / denom) > IOU_T;
}

// ---------------- K1: smem-private histogram; LAST block per image scans ----------------
__global__ void __launch_bounds__(1024) k_hist(const float* __restrict__ preds) {
    __shared__ unsigned sh[NB];
    __shared__ unsigned wsum[32];
    __shared__ int sb, slast;
    const int img  = blockIdx.x >> 3;
    const int part = blockIdx.x & 7;
    const int tid  = threadIdx.x;
    const int lane = tid & 31;
    const int wid  = tid >> 5;
    const float4* conf4 = (const float4*)(preds + (size_t)img * NCH * NANCH + 4 * (size_t)NANCH);
    const int st = part * CHUNK;
    const int en = min(NV4, st + CHUNK);

    // smem-private histogram (no global atomics)
    ((uint4*)sh)[tid] = make_uint4(0u, 0u, 0u, 0u);
    __syncthreads();
    for (int i = st + tid; i < en; i += 1024) {
        float4 v = conf4[i];
        if (v.x > CONF_T) atomicAdd(&sh[bucket_of(v.x)], 1u);
        if (v.y > CONF_T) atomicAdd(&sh[bucket_of(v.y)], 1u);
        if (v.z > CONF_T) atomicAdd(&sh[bucket_of(v.z)], 1u);
        if (v.w > CONF_T) atomicAdd(&sh[bucket_of(v.w)], 1u);
    }
    __syncthreads();
    // coalesced plain store of this block's slice
    ((uint4*)(g_histp + (size_t)(img * BPI + part) * NB))[tid] = ((const uint4*)sh)[tid];

    __syncthreads();
    if (tid == 0) {
        __threadfence();                                   // release slice stores
        slast = (atomicAdd(&g_done1[img], 1u) == BPI - 1);
        sb = 0;
    }
    __syncthreads();
    if (!slast) return;

    // ---- last block: acquire + sum 8 slices + scan ----
    __threadfence();
    if (tid == 0) g_done1[img] = 0u;                       // reset ticket for next replay

    uint4 hv = make_uint4(0u, 0u, 0u, 0u);
    #pragma unroll
    for (int p = 0; p < BPI; p++) {
        uint4 t = ((const uint4*)(g_histp + (size_t)(img * BPI + p) * NB))[tid];
        hv.x += t.x; hv.y += t.y; hv.z += t.z; hv.w += t.w;
    }
    unsigned tot = hv.x + hv.y + hv.z + hv.w;
    unsigned suf = tot;
    #pragma unroll
    for (int d = 1; d < 32; d <<= 1) {
        unsigned v = __shfl_down_sync(FULLM, suf, d);
        if (lane + d < 32) suf += v;
    }
    if (lane == 0) wsum[wid] = suf;
    __syncthreads();
    if (tid < 32) {
        unsigned v  = wsum[tid];
        unsigned sv = v;
        #pragma unroll
        for (int d = 1; d < 32; d <<= 1) {
            unsigned u = __shfl_down_sync(FULLM, sv, d);
            if (tid + d < 32) sv += u;
        }
        wsum[tid] = sv - v;
    }
    __syncthreads();
    unsigned run = wsum[wid] + (suf - tot);
    unsigned e3 = run;
    unsigned e2 = e3 + hv.w;
    unsigned e1 = e2 + hv.z;
    unsigned e0 = e1 + hv.y;
    uint4 ev = make_uint4(e0, e1, e2, e3);
    ((uint4*)(g_bstart + img * NB))[tid] = ev;
    ((uint4*)(g_cursor + img * NB))[tid] = ev;
    if      (e3 + hv.w >= (unsigned)KTOP) atomicMax(&sb, 4 * tid + 3);
    else if (e2 + hv.z >= (unsigned)KTOP) atomicMax(&sb, 4 * tid + 2);
    else if (e1 + hv.y >= (unsigned)KTOP) atomicMax(&sb, 4 * tid + 1);
    else if (e0 + hv.x >= (unsigned)KTOP) atomicMax(&sb, 4 * tid + 0);
    __syncthreads();
    if (tid == 0) g_cutoff[img] = sb;
}

// ---------------- K2: scatter; LAST block per image runs rank + NMS + emit ----------------
// smem layout (bytes)
#define OFF_EN     0                      // 4096*4
#define OFF_BST    16384                  // 4096*4
#define OFF_KEYS   32768                  // 4096*8
#define OFF_KEYS2  65536                  // 4096*8
#define OFF_LBOX   98304                  // 432*16
#define OFF_LAREA  (OFF_LBOX  + 6912)
#define OFF_LKEY   (OFF_LAREA + 1728)     // 304*8
#define OFF_TBOX   (OFF_LKEY  + 2432)     // 2*128*16
#define OFF_TAREA  (OFF_TBOX  + 4096)     // 2*128*4
#define OFF_SMAT   (OFF_TAREA + 1024)     // 128*4*4
#define OFF_SSUPW  (OFF_SMAT  + 2048)     // 32*4
#define SMEM_TOTAL (OFF_SSUPW + 128)

__device__ __forceinline__ void decode_box(const float* pimg, unsigned long long key,
                                           float4& b, float& area) {
    int anchor = 65535 - (int)(key & 0xFFFFull);
    anchor = min(anchor, NANCH - 1);
    float cx = pimg[anchor];
    float cy = pimg[(size_t)NANCH + anchor];
    float w  = pimg[2 * (size_t)NANCH + anchor];
    float ht = pimg[3 * (size_t)NANCH + anchor];
    float hw = w * 0.5f, hh = ht * 0.5f;
    b.x = fminf(fmaxf(cx - hw, 0.0f), IMGW);
    b.y = fminf(fmaxf(cy - hh, 0.0f), IMGW);
    b.z = fminf(fmaxf(cx + hw, 0.0f), IMGW);
    b.w = fminf(fmaxf(cy + hh, 0.0f), IMGW);
    area = __fmul_rn(b.z - b.x, b.w - b.y);
}

__global__ void __launch_bounds__(1024) k_scatmain(const float* __restrict__ preds) {
    extern __shared__ char sm[];
    __shared__ int s_count, s_stop, slast;
    const int img  = blockIdx.x >> 3;
    const int part = blockIdx.x & 7;
    const int tid  = threadIdx.x;
    const int lane = tid & 31;
    const int wrp  = tid >> 5;
    const float* pimg  = preds + (size_t)img * NCH * NANCH;
    const float4* conf4 = (const float4*)(pimg + 4 * (size_t)NANCH);

    // ---- scatter phase (all 8 blocks) ----
    {
        const int cutoff = g_cutoff[img];
        unsigned* cursor = g_cursor + img * NB;
        unsigned long long* keys = g_keys + img * CAP;
        const int st = part * CHUNK;
        const int en = min(NV4, st + CHUNK);
        for (int i = st + tid; i < en; i += 1024) {
            float4 v = conf4[i];
            float sv[4] = {v.x, v.y, v.z, v.w};
            int a = 4 * i;
            #pragma unroll
            for (int c = 0; c < 4; c++) {
                float s = sv[c];
                if (s > CONF_T) {
                    int b = bucket_of(s);
                    if (b >= cutoff) {
                        unsigned pos = atomicAdd(&cursor[b], 1u);
                        if (pos < CAP)
                            keys[pos] = ((unsigned long long)ordkey(s) << 16)
                                      | (unsigned)(65535 - (a + c));
                    }
                }
            }
        }
    }
    __syncthreads();
    if (tid == 0) {
        __threadfence();                                   // release key writes
        slast = (atomicAdd(&g_done2[img], 1u) == BPI - 1);
    }
    __syncthreads();
    if (!slast) return;

    // ---- last block continues: acquire + rank + NMS + emit ----
    __threadfence();
    if (tid == 0) g_done2[img] = 0u;                       // reset ticket

    unsigned*           sen   = (unsigned*)(sm + OFF_EN);
    unsigned*           sbst  = (unsigned*)(sm + OFF_BST);
    unsigned long long* keys  = (unsigned long long*)(sm + OFF_KEYS);
    unsigned long long* keys2 = (unsigned long long*)(sm + OFF_KEYS2);
    float4*             lbox  = (float4*)(sm + OFF_LBOX);
    float*              larea = (float*)(sm + OFF_LAREA);
    unsigned long long* lkey  = (unsigned long long*)(sm + OFF_LKEY);
    float4*             tbox  = (float4*)(sm + OFF_TBOX);
    float*              tarea = (float*)(sm + OFF_TAREA);
    unsigned*           smat  = (unsigned*)(sm + OFF_SMAT);
    unsigned*           ssupw = (unsigned*)(sm + OFF_SSUPW);

    ((uint4*)sen)[tid]  = ((const uint4*)(g_cursor + img * NB))[tid];
    ((uint4*)sbst)[tid] = ((const uint4*)(g_bstart + img * NB))[tid];
    for (int r = tid; r < CAP; r += 1024) {
        keys[r]  = g_keys[img * CAP + r];
        keys2[r] = 0ull;
    }
    if (tid == 0) { s_count = 0; s_stop = 0; }
    __syncthreads();

    const int cutoff = g_cutoff[img];
    const int ntot   = min((int)sen[cutoff], CAP);

    // ---- exact within-bucket ranking -> keys2 sorted desc ----
    for (int p = tid; p < ntot; p += 1024) {
        unsigned long long key = keys[p];
        float sc = inv_ordkey((unsigned)(key >> 16));
        int b  = bucket_of(sc);
        int st = (int)sbst[b];
        int en = min((int)sen[b], CAP);
        int rank = st;
        for (int q = st; q < en; q++) rank += (keys[q] > key) ? 1 : 0;
        keys2[rank] = key;
    }
    __syncthreads();

    // ---- preload super-tile 0 ----
    if (tid >= 64 && tid < 192) {
        int c = tid - 64;
        float4 b; float ar;
        decode_box(pimg, keys2[c], b, ar);
        tbox[c] = b; tarea[c] = ar;
    }
    __syncthreads();

    // ---- super-tile NMS loop ----
    int buf = 0;
    for (int base = 0; base < KTOP; base += STILE, buf ^= 1) {
        if (tid >= 64 && tid < 192 && base + STILE < KTOP) {
            int c = tid - 64;
            float4 b; float ar;
            decode_box(pimg, keys2[base + STILE + c], b, ar);
            tbox[(buf ^ 1) * STILE + c] = b;
            tarea[(buf ^ 1) * STILE + c] = ar;
        }
        // A2: leader tests
        {
            const int j  = tid >> 3;
            const int k  = tid & 7;
            const int cj = base + j;
            float sc = inv_ordkey((unsigned)(keys2[min(cj, CAP - 1)] >> 16));
            bool bad = !((cj < KTOP) && (sc > CONF_T));
            if (!bad) {
                float4 bj = tbox[buf * STILE + j];
                float  aj = tarea[buf * STILE + j];
                const int cnt = s_count;
                for (int l = k; l < cnt; l += 8) {
                    float4 bl = lbox[l];
                    bad |= sup_test(bl.x, bl.y, bl.z, bl.w, larea[l],
                                    bj.x, bj.y, bj.z, bj.w, aj);
                }
            }
            unsigned bm = __ballot_sync(FULLM, bad);
            if (lane == 0) ssupw[wrp] = bm;
        }
        // A3: 128x128 suppression bit-matrix
        {
            #pragma unroll
            for (int r = 0; r < 4; r++) {
                const int i = 4 * wrp + r;
                float4 bi = tbox[buf * STILE + i];
                float  ai = tarea[buf * STILE + i];
                #pragma unroll
                for (int cw = 0; cw < 4; cw++) {
                    const int j = cw * 32 + lane;
                    bool bit = false;
                    if (j > i) {
                        float4 bj = tbox[buf * STILE + j];
                        float  aj = tarea[buf * STILE + j];
                        bit = sup_test(bi.x, bi.y, bi.z, bi.w, ai,
                                       bj.x, bj.y, bj.z, bj.w, aj);
                    }
                    unsigned bm = __ballot_sync(FULLM, bit);
                    if (lane == 0) smat[i * 4 + cw] = bm;
                }
            }
        }
        __syncthreads();

        // phase B: warp 0 resolves 128-candidate greedy
        if (tid < 32) {
            unsigned S1 = 0, S2 = 0, S3 = 0;
            int cur = s_count;
            #pragma unroll
            for (int m = 0; m < 4; m++) {
                const int c = 32 * m + lane;
                unsigned supb = (ssupw[8 * m + (lane >> 2)] >> ((lane & 3) * 8)) & 0xFFu;
                unsigned Sm = (m == 1) ? S1 : (m == 2) ? S2 : (m == 3) ? S3 : 0u;
                bool alive = (supb == 0u) && !((Sm >> lane) & 1u);
                unsigned aliveb = __ballot_sync(FULLM, alive);
                unsigned rm = smat[c * 4 + m];
                unsigned kept;
                if (__ballot_sync(FULLM, (rm & aliveb) != 0u) == 0u) {
                    kept = aliveb;
                } else {
                    unsigned Sl = 0; kept = 0;
                    #pragma unroll 4
                    for (int ii = 0; ii < 32; ii++) {
                        unsigned ri = __shfl_sync(FULLM, rm, ii);
                        bool ki = ((aliveb >> ii) & 1u) && !((Sl >> ii) & 1u);
                        if (ki) { kept |= (1u << ii); Sl |= ri; }
                    }
                }
                if ((kept >> lane) & 1u) {
                    int pos = cur + __popc(kept & ((1u << lane) - 1u));
                    if (pos < LCAP) {
                        lbox[pos]  = tbox[buf * STILE + c];
                        larea[pos] = tarea[buf * STILE + c];
                    }
                    if (pos < MAXDET) lkey[pos] = keys2[base + c];
                }
                cur += __popc(kept);
                unsigned kb = (kept >> lane) & 1u;
                if (m < 1) S1 |= __reduce_or_sync(FULLM, kb ? smat[c * 4 + 1] : 0u);
                if (m < 2) S2 |= __reduce_or_sync(FULLM, kb ? smat[c * 4 + 2] : 0u);
                if (m < 3) S3 |= __reduce_or_sync(FULLM, kb ? smat[c * 4 + 3] : 0u);
            }
            if (lane == 0) {
                s_count = cur;
                if (cur >= MAXDET) s_stop = 1;
            }
        }
        __syncthreads();
        if (s_stop) break;
    }
    __syncthreads();

    // ---- emit compact per-image selection ----
    const int cnt = min(s_count, MAXDET);
    if (tid < cnt) {
        unsigned long long key = lkey[tid];
        g_selbox  [img * MAXDET + tid] = lbox[tid];
        g_selscore[img * MAXDET + tid] = inv_ordkey((unsigned)(key >> 16));
        g_selanch [img * MAXDET + tid] = 65535 - (int)(key & 0xFFFFull);
    }
    if (tid == 0) g_cnt[img] = cnt;
}

// ---------------- K3: wide output writer ----------------
#define TOTOUT (BS * MAXDET * 56)
__global__ void __launch_bounds__(1024) k_out(const float* __restrict__ preds,
                                              float* __restrict__ out) {
    int s = blockIdx.x * 1024 + threadIdx.x;
    if (s >= TOTOUT) return;
    const int img = s / (MAXDET * 56);
    const int rem = s % (MAXDET * 56);
    const int r   = rem / 56;
    const int f   = rem % 56;
    const int cnt = g_cnt[img];

    float v = 0.0f;
    if (r < cnt) {
        if (f < 4) {
            float4 b = g_selbox[img * MAXDET + r];
            v = (f == 0) ? b.x : (f == 1) ? b.y : (f == 2) ? b.z : b.w;
        } else if (f == 4) {
            v = g_selscore[img * MAXDET + r];
        } else {
            int c = f - 5;
            int a = g_selanch[img * MAXDET + r];
            v = preds[(size_t)img * NCH * NANCH + (size_t)(5 + c) * NANCH + a];
            if (c < 2) v = fminf(fmaxf(v, 0.0f), IMGW);
        }
    }
    const int OSC = BS * MAXDET * 4;
    const int OKP = OSC + BS * MAXDET;
    if (f < 4)       out[(img * MAXDET + r) * 4 + f] = v;
    else if (f == 4) out[OSC + img * MAXDET + r] = v;
    else             out[OKP + (img * MAXDET + r) * 51 + (f - 5)] = v;
}

// ---------------- launch ----------------
extern "C" void kernel_launch(void* const* d_in, const int* in_sizes, int n_in,
                              void* d_out, int out_size) {
    const float* preds = (const float*)d_in[0];
    float* out = (float*)d_out;
    cudaFuncSetAttribute(k_scatmain, cudaFuncAttributeMaxDynamicSharedMemorySize, SMEM_TOTAL);
    k_hist    <<<BS * BPI, 1024>>>(preds);
    k_scatmain<<<BS * BPI, 1024, SMEM_TOTAL>>>(preds);
    k_out     <<<(TOTOUT + 1023) / 1024, 1024>>>(preds, out);
}

// round 13
// speedup vs baseline: 1.1633x; 1.1048x over previous
#include <cuda_runtime.h>

#define BS      16
#define NANCH   33600
#define NV4     8400
#define NCH     56
#define KTOP    3000
#define CAP     4096
#define NB      4096
#define MAXDET  300
#define CONF_T  0.25f
#define IOU_T   0.7f
#define IMGW    1280.0f
#define FULLM   0xFFFFFFFFu
#define BPI     8
#define CHUNK   1050
#define NSEL    512
#define NW      16      // NSEL / 32
#define LCAPE   336

// ---------------- global scratch (L2-resident) ----------------
__device__ unsigned           g_cursoff[BS * NB];     // zeroed by k_out each replay (zero-init at load)
__device__ unsigned long long g_keys   [BS * CAP];    // bucket segments rewritten each replay
__device__ unsigned long long g_keys2  [BS * CAP];    // sorted; [ntot,CAP) zeroed each replay
__device__ int                g_ntot   [BS];
__device__ unsigned           g_mat    [BS * NSEL * NW];
__device__ unsigned           g_done2  [BS];          // ticket, self-resetting
__device__ unsigned           g_done3  [BS];          // ticket, self-resetting
__device__ int                g_cnt    [BS];
__device__ float4             g_selbox  [BS * MAXDET];
__device__ float              g_selscore[BS * MAXDET];
__device__ int                g_selanch [BS * MAXDET];

__device__ __forceinline__ unsigned ordkey(float f) {
    unsigned b = __float_as_uint(f);
    return (b & 0x80000000u) ? ~b : (b | 0x80000000u);
}
__device__ __forceinline__ float inv_ordkey(unsigned u) {
    unsigned bits = (u & 0x80000000u) ? (u & 0x7FFFFFFFu) : ~u;
    return __uint_as_float(bits);
}
__device__ __forceinline__ int bucket_of(float s) {
    int b = (int)(s * 4096.0f);
    return min(4095, max(0, b));
}
// suppression test, bit-identical to reference rounding (rel_err=0 R1..R12)
__device__ __forceinline__ bool sup_test(float ax, float ay, float az, float aw, float aa,
                                         float bx, float by, float bz, float bw, float ab) {
    float xx1 = fmaxf(ax, bx);
    float yy1 = fmaxf(ay, by);
    float xx2 = fminf(az, bz);
    float yy2 = fminf(aw, bw);
    float ww  = fmaxf(xx2 - xx1, 0.0f);
    float hh  = fmaxf(yy2 - yy1, 0.0f);
    float inter = __fmul_rn(ww, hh);
    if (inter <= 0.0f) return false;
    float denom = __fadd_rn(__fsub_rn(__fadd_rn(aa, ab), inter), 1e-9f);
    return (inter / denom) > IOU_T;
}
__device__ __forceinline__ void decode_box(const float* pimg, unsigned long long key,
                                           float4& b, float& area) {
    int anchor = 65535 - (int)(key & 0xFFFFull);
    anchor = min(anchor, NANCH - 1);
    float cx = pimg[anchor];
    float cy = pimg[(size_t)NANCH + anchor];
    float w  = pimg[2 * (size_t)NANCH + anchor];
    float ht = pimg[3 * (size_t)NANCH + anchor];
    float hw = w * 0.5f, hh = ht * 0.5f;
    b.x = fminf(fmaxf(cx - hw, 0.0f), IMGW);
    b.y = fminf(fmaxf(cy - hh, 0.0f), IMGW);
    b.z = fminf(fmaxf(cx + hw, 0.0f), IMGW);
    b.w = fminf(fmaxf(cy + hh, 0.0f), IMGW);
    area = __fmul_rn(b.z - b.x, b.w - b.y);
}

// ================= K1: per-block hist+scan (redundant), scatter; last block ranks =================
#define F_SMEM (NB * 4 + CAP * 8)   // 49152
__global__ void __launch_bounds__(1024) k_front(const float* __restrict__ preds) {
    extern __shared__ char sm[];
    unsigned*           sh    = (unsigned*)sm;                 // hist -> bstart (in place)
    unsigned long long* skeys = (unsigned long long*)(sm + NB * 4);
    __shared__ unsigned wsum[32];
    __shared__ int sb, slast;

    const int img  = blockIdx.x >> 3;
    const int part = blockIdx.x & 7;
    const int tid  = threadIdx.x;
    const int lane = tid & 31;
    const int wid  = tid >> 5;
    const float*  pimg  = preds + (size_t)img * NCH * NANCH;
    const float4* conf4 = (const float4*)(pimg + 4 * (size_t)NANCH);

    // ---- full-image histogram (redundant per block; smem only) ----
    ((uint4*)sh)[tid] = make_uint4(0u, 0u, 0u, 0u);
    if (tid == 0) sb = 0;
    __syncthreads();
    for (int i = tid; i < NV4; i += 1024) {
        float4 v = conf4[i];
        if (v.x > CONF_T) atomicAdd(&sh[bucket_of(v.x)], 1u);
        if (v.y > CONF_T) atomicAdd(&sh[bucket_of(v.y)], 1u);
        if (v.z > CONF_T) atomicAdd(&sh[bucket_of(v.z)], 1u);
        if (v.w > CONF_T) atomicAdd(&sh[bucket_of(v.w)], 1u);
    }
    __syncthreads();

    // ---- suffix scan -> bstart (in place) + cutoff ----
    uint4 hv = ((const uint4*)sh)[tid];
    unsigned tot = hv.x + hv.y + hv.z + hv.w;
    unsigned suf = tot;
    #pragma unroll
    for (int d = 1; d < 32; d <<= 1) {
        unsigned v = __shfl_down_sync(FULLM, suf, d);
        if (lane + d < 32) suf += v;
    }
    if (lane == 0) wsum[wid] = suf;
    __syncthreads();
    if (tid < 32) {
        unsigned v  = wsum[tid];
        unsigned sv = v;
        #pragma unroll
        for (int d = 1; d < 32; d <<= 1) {
            unsigned u = __shfl_down_sync(FULLM, sv, d);
            if (tid + d < 32) sv += u;
        }
        wsum[tid] = sv - v;
    }
    __syncthreads();
    unsigned run = wsum[wid] + (suf - tot);
    unsigned e3 = run;
    unsigned e2 = e3 + hv.w;
    unsigned e1 = e2 + hv.z;
    unsigned e0 = e1 + hv.y;
    ((uint4*)sh)[tid] = make_uint4(e0, e1, e2, e3);   // bstart
    if      (e3 + hv.w >= (unsigned)KTOP) atomicMax(&sb, 4 * tid + 3);
    else if (e2 + hv.z >= (unsigned)KTOP) atomicMax(&sb, 4 * tid + 2);
    else if (e1 + hv.y >= (unsigned)KTOP) atomicMax(&sb, 4 * tid + 1);
    else if (e0 + hv.x >= (unsigned)KTOP) atomicMax(&sb, 4 * tid + 0);
    __syncthreads();
    const int cutoff = sb;

    // ---- scatter own chunk (bstart local + shared offset atomics) ----
    {
        unsigned* coff = g_cursoff + img * NB;
        unsigned long long* keysg = g_keys + (size_t)img * CAP;
        const int st = part * CHUNK;
        const int en = min(NV4, st + CHUNK);
        for (int i = st + tid; i < en; i += 1024) {
            float4 v = conf4[i];
            float sv[4] = {v.x, v.y, v.z, v.w};
            int a = 4 * i;
            #pragma unroll
            for (int c = 0; c < 4; c++) {
                float s = sv[c];
                if (s > CONF_T) {
                    int b = bucket_of(s);
                    if (b >= cutoff) {
                        unsigned pos = sh[b] + atomicAdd(&coff[b], 1u);
                        if (pos < CAP)
                            keysg[pos] = ((unsigned long long)ordkey(s) << 16)
                                       | (unsigned)(65535 - (a + c));
                    }
                }
            }
        }
    }
    __syncthreads();
    if (tid == 0) {
        __threadfence();
        slast = (atomicAdd(&g_done2[img], 1u) == BPI - 1);
    }
    __syncthreads();
    if (!slast) return;

    // ---- last block: rank all candidates -> g_keys2 ----
    __threadfence();
    if (tid == 0) g_done2[img] = 0u;

    for (int r = tid; r < CAP; r += 1024) skeys[r] = g_keys[(size_t)img * CAP + r];
    __syncthreads();

    const int ntot = min((int)(sh[cutoff] + g_cursoff[img * NB + cutoff]), CAP);
    for (int p = tid; p < ntot; p += 1024) {
        unsigned long long key = skeys[p];
        float sc = inv_ordkey((unsigned)(key >> 16));
        int b   = bucket_of(sc);
        int st2 = (int)sh[b];
        int en2 = min((int)(sh[b] + g_cursoff[img * NB + b]), CAP);
        int rank = st2;
        for (int q = st2; q < en2; q++) rank += (skeys[q] > key) ? 1 : 0;
        g_keys2[(size_t)img * CAP + rank] = key;
    }
    for (int p = ntot + tid; p < CAP; p += 1024)
        g_keys2[(size_t)img * CAP + p] = 0ull;
    if (tid == 0) g_ntot[img] = ntot;
}

// ================= K2: parallel 512x512 suppression matrix; last block resolves =================
// smem layout (bytes)
#define M_SBOX  0                        // 512*16 = 8192
#define M_SAREA 8192                     // 512*4  = 2048
#define M_SKEY  10240                    // 512*8  = 4096
#define M_SMAT  14336                    // 512*16*4 = 32768
#define M_LBOX  47104                    // 336*16 = 5376
#define M_LAREA 52480                    // 336*4  = 1344
#define M_LKEY  53824                    // 336*8  = 2688
#define M_TOTAL 56512

__global__ void __launch_bounds__(1024) k_matres(const float* __restrict__ preds) {
    extern __shared__ char sm[];
    float4*             sbox  = (float4*)(sm + M_SBOX);
    float*              sarea = (float*)(sm + M_SAREA);
    unsigned long long* skey  = (unsigned long long*)(sm + M_SKEY);
    unsigned*           smat  = (unsigned*)(sm + M_SMAT);
    float4*             lbox  = (float4*)(sm + M_LBOX);
    float*              slar  = (float*)(sm + M_LAREA);
    unsigned long long* lkey  = (unsigned long long*)(sm + M_LKEY);
    __shared__ unsigned sValid[NW], sSall[NW], sKept0[NW], sK0[NW], sKept[NW], sPref[NW];
    __shared__ int s_cur, slast;

    const int img  = blockIdx.x >> 3;
    const int part = blockIdx.x & 7;
    const int tid  = threadIdx.x;
    const int lane = tid & 31;
    const int w    = tid >> 5;
    const float* pimg = preds + (size_t)img * NCH * NANCH;
    const int ntot = g_ntot[img];

    // ---- decode top-512 candidates ----
    if (tid < NSEL) {
        unsigned long long key = g_keys2[(size_t)img * CAP + tid];
        skey[tid] = key;
        float4 b; float ar;
        decode_box(pimg, key, b, ar);
        sbox[tid] = b; sarea[tid] = ar;
    }
    __syncthreads();

    // ---- slab of upper-triangular suppression matrix ----
    {
        const int cw   = w & 15;          // column word
        const int half = w >> 4;          // row half
        const int j    = cw * 32 + lane;
        float4 bj = sbox[j];
        float  aj = sarea[j];
        const int i0 = part * 64 + half * 32;
        #pragma unroll 4
        for (int r = 0; r < 32; r++) {
            const int i = i0 + r;
            if (cw >= (i >> 5)) {
                float4 bi = sbox[i];
                float  ai = sarea[i];
                bool bit = (j > i) && sup_test(bi.x, bi.y, bi.z, bi.w, ai,
                                               bj.x, bj.y, bj.z, bj.w, aj);
                unsigned bm = __ballot_sync(FULLM, bit);
                if (lane == 0) g_mat[((size_t)img * NSEL + i) * NW + cw] = bm;
            }
        }
    }
    __syncthreads();
    if (tid == 0) {
        __threadfence();
        slast = (atomicAdd(&g_done3[img], 1u) == BPI - 1);
    }
    __syncthreads();
    if (!slast) return;

    // ---- last block: exact greedy resolve via bit algebra ----
    __threadfence();
    if (tid == 0) { g_done3[img] = 0u; s_cur = 0; }
    for (int idx = tid; idx < NSEL * NW; idx += 1024)
        smat[idx] = g_mat[(size_t)img * NSEL * NW + idx];
    __syncthreads();

    // valid masks
    if (w < NW) {
        int c = w * 32 + lane;
        bool valid = (c < ntot) && (skey[c] != 0ull);
        unsigned vb = __ballot_sync(FULLM, valid);
        if (lane == 0) sValid[w] = vb;
    }
    __syncthreads();
    // S_all[w] = OR of all valid rows' word w (rows with c>>5 <= w only: triangular)
    if (w < NW) {
        unsigned acc = 0;
        for (int k = 0; k <= w; k++) {
            int c = k * 32 + lane;
            if ((sValid[k] >> lane) & 1u) acc |= smat[c * NW + w];
        }
        acc = __reduce_or_sync(FULLM, acc);
        if (lane == 0) sSall[w] = acc;
    }
    __syncthreads();
    if (w < NW && lane == 0) sKept0[w] = sValid[w] & ~sSall[w];   // definitely kept
    __syncthreads();
    // S_k0[w] = OR of kept0 rows' word w
    if (w < NW) {
        unsigned acc = 0;
        for (int k = 0; k <= w; k++) {
            int c = k * 32 + lane;
            if ((sKept0[k] >> lane) & 1u) acc |= smat[c * NW + w];
        }
        acc = __reduce_or_sync(FULLM, acc);
        if (lane == 0) sK0[w] = acc;
    }
    __syncthreads();

    // warp 0: resolve contested candidates serially (bit lookups only) + prefix
    if (tid < 32) {
        unsigned Sck = 0;       // lane l<16 holds contested-kept OR, word l
        unsigned keptReg = 0;   // lane m holds kept mask word m
        for (int m = 0; m < NW; m++) {
            unsigned cont = sValid[m] & sSall[m];
            unsigned kc = 0;
            while (cont) {
                int bit = __ffs(cont) - 1;
                cont &= cont - 1u;
                int c = m * 32 + bit;
                unsigned sckm = __shfl_sync(FULLM, Sck, m);
                bool suppressed = (((sK0[m] | sckm) >> bit) & 1u) != 0u;
                if (!suppressed) {
                    kc |= 1u << bit;
                    if (lane < NW && lane >= m) Sck |= smat[c * NW + lane];
                }
            }
            unsigned kw = (sValid[m] & ~sSall[m]) | kc;
            if (lane == m) keptReg = kw;
        }
        int cntw = __popc((lane < NW) ? keptReg : 0u);
        int inc = cntw;
        #pragma unroll
        for (int d = 1; d < 32; d <<= 1) {
            int v = __shfl_up_sync(FULLM, inc, d);
            if (lane >= d) inc += v;
        }
        if (lane < NW) { sKept[lane] = keptReg; sPref[lane] = inc - cntw; }
        if (lane == 31) s_cur = inc;    // total kept among NSEL
    }
    __syncthreads();

    // build compact kept list (index order)
    if (tid < NSEL) {
        int wrd = tid >> 5;
        int l   = tid & 31;
        unsigned km = sKept[wrd];
        if ((km >> l) & 1u) {
            int rank = (int)sPref[wrd] + __popc(km & ((1u << l) - 1u));
            if (rank < LCAPE) {
                lbox[rank] = sbox[tid];
                slar[rank] = sarea[tid];
                lkey[rank] = skey[tid];
            }
        }
    }
    __syncthreads();

    // exact fallback: continue past NSEL if fewer than MAXDET kept (rare/never)
    if (tid < 32) {
        int curf = s_cur;
        int lim  = min(min(ntot, CAP), KTOP);
        if (curf < MAXDET && lim > NSEL) {
            for (int c = NSEL; c < lim && curf < MAXDET; c++) {
                unsigned long long key = g_keys2[(size_t)img * CAP + c];
                if (key == 0ull) continue;
                float4 bc; float ac;
                decode_box(pimg, key, bc, ac);
                bool sup = false;
                for (int l = lane; l < curf; l += 32) {
                    float4 bl = lbox[l];
                    sup |= sup_test(bl.x, bl.y, bl.z, bl.w, slar[l],
                                    bc.x, bc.y, bc.z, bc.w, ac);
                }
                if (!__any_sync(FULLM, sup)) {
                    if (lane == 0 && curf < LCAPE) {
                        lbox[curf] = bc; slar[curf] = ac; lkey[curf] = key;
                    }
                    __syncwarp();
                    curf++;
                }
            }
        }
        if (lane == 0) s_cur = curf;
    }
    __syncthreads();

    const int cnt = min(s_cur, MAXDET);
    if (tid < cnt) {
        unsigned long long key = lkey[tid];
        g_selbox  [img * MAXDET + tid] = lbox[tid];
        g_selscore[img * MAXDET + tid] = inv_ordkey((unsigned)(key >> 16));
        g_selanch [img * MAXDET + tid] = 65535 - (int)(key & 0xFFFFull);
    }
    if (tid == 0) g_cnt[img] = cnt;
}

// ================= K3: wide output writer (+ cursoff reset for next replay) =================
#define TOTOUT (BS * MAXDET * 56)
__global__ void __launch_bounds__(1024) k_out(const float* __restrict__ preds,
                                              float* __restrict__ out) {
    int s = blockIdx.x * 1024 + threadIdx.x;
    if (s < BS * NB) g_cursoff[s] = 0u;      // reset scatter offsets for next replay
    if (s >= TOTOUT) return;
    const int img = s / (MAXDET * 56);
    const int rem = s % (MAXDET * 56);
    const int r   = rem / 56;
    const int f   = rem % 56;
    const int cnt = g_cnt[img];

    float v = 0.0f;
    if (r < cnt) {
        if (f < 4) {
            float4 b = g_selbox[img * MAXDET + r];
            v = (f == 0) ? b.x : (f == 1) ? b.y : (f == 2) ? b.z : b.w;
        } else if (f == 4) {
            v = g_selscore[img * MAXDET + r];
        } else {
            int c = f - 5;
            int a = g_selanch[img * MAXDET + r];
            v = preds[(size_t)img * NCH * NANCH + (size_t)(5 + c) * NANCH + a];
            if (c < 2) v = fminf(fmaxf(v, 0.0f), IMGW);
        }
    }
    const int OSC = BS * MAXDET * 4;
    const int OKP = OSC + BS * MAXDET;
    if (f < 4)       out[(img * MAXDET + r) * 4 + f] = v;
    else if (f == 4) out[OSC + img * MAXDET + r] = v;
    else             out[OKP + (img * MAXDET + r) * 51 + (f - 5)] = v;
}

// ---------------- launch ----------------
extern "C" void kernel_launch(void* const* d_in, const int* in_sizes, int n_in,
                              void* d_out, int out_size) {
    const float* preds = (const float*)d_in[0];
    float* out = (float*)d_out;
    cudaFuncSetAttribute(k_front,  cudaFuncAttributeMaxDynamicSharedMemorySize, F_SMEM);
    cudaFuncSetAttribute(k_matres, cudaFuncAttributeMaxDynamicSharedMemorySize, M_TOTAL);
    k_front <<<BS * BPI, 1024, F_SMEM>>>(preds);
    k_matres<<<BS * BPI, 1024, M_TOTAL>>>(preds);
    k_out   <<<(TOTOUT + 1023) / 1024, 1024>>>(preds, out);
}

// round 14
// speedup vs baseline: 1.2187x; 1.0477x over previous
#include <cuda_runtime.h>

#define BS      16
#define NANCH   33600
#define NV4     8400
#define NCH     56
#define KTOP    3000
#define CAP     4096
#define NB      4096
#define MAXDET  300
#define CONF_T  0.25f
#define IOU_T   0.7f
#define IMGW    1280.0f
#define FULLM   0xFFFFFFFFu
#define BPI     8
#define NSEL    512
#define NW      16      // NSEL / 32
#define LCAPE   336

// ---------------- global scratch (L2-resident) ----------------
__device__ unsigned long long g_keys2  [BS * CAP];    // fully rewritten each replay
__device__ int                g_ntot   [BS];
__device__ unsigned           g_mat    [BS * NSEL * NW];
__device__ unsigned           g_done3  [BS];          // ticket, self-resetting
__device__ int                g_cnt    [BS];
__device__ float4             g_selbox  [BS * MAXDET];
__device__ float              g_selscore[BS * MAXDET];
__device__ int                g_selanch [BS * MAXDET];

__device__ __forceinline__ unsigned ordkey(float f) {
    unsigned b = __float_as_uint(f);
    return (b & 0x80000000u) ? ~b : (b | 0x80000000u);
}
__device__ __forceinline__ float inv_ordkey(unsigned u) {
    unsigned bits = (u & 0x80000000u) ? (u & 0x7FFFFFFFu) : ~u;
    return __uint_as_float(bits);
}
__device__ __forceinline__ int bucket_of(float s) {
    int b = (int)(s * 4096.0f);
    return min(4095, max(0, b));
}
// suppression test, bit-identical to reference rounding (rel_err=0 R1..R13)
__device__ __forceinline__ bool sup_test(float ax, float ay, float az, float aw, float aa,
                                         float bx, float by, float bz, float bw, float ab) {
    float xx1 = fmaxf(ax, bx);
    float yy1 = fmaxf(ay, by);
    float xx2 = fminf(az, bz);
    float yy2 = fminf(aw, bw);
    float ww  = fmaxf(xx2 - xx1, 0.0f);
    float hh  = fmaxf(yy2 - yy1, 0.0f);
    float inter = __fmul_rn(ww, hh);
    if (inter <= 0.0f) return false;
    float denom = __fadd_rn(__fsub_rn(__fadd_rn(aa, ab), inter), 1e-9f);
    return (inter / denom) > IOU_T;
}
__device__ __forceinline__ void decode_box(const float* pimg, unsigned long long key,
                                           float4& b, float& area) {
    int anchor = 65535 - (int)(key & 0xFFFFull);
    anchor = min(anchor, NANCH - 1);
    float cx = pimg[anchor];
    float cy = pimg[(size_t)NANCH + anchor];
    float w  = pimg[2 * (size_t)NANCH + anchor];
    float ht = pimg[3 * (size_t)NANCH + anchor];
    float hw = w * 0.5f, hh = ht * 0.5f;
    b.x = fminf(fmaxf(cx - hw, 0.0f), IMGW);
    b.y = fminf(fmaxf(cy - hh, 0.0f), IMGW);
    b.z = fminf(fmaxf(cx + hw, 0.0f), IMGW);
    b.w = fminf(fmaxf(cy + hh, 0.0f), IMGW);
    area = __fmul_rn(b.z - b.x, b.w - b.y);
}

// ================= K1: one block per image — hist + scan + scatter + rank, all in smem =================
// smem: sh[NB] (hist->bstart) 16KB | scur[NB] 16KB | skeys[CAP] 32KB = 65536 B
#define F_SMEM (NB * 4 + NB * 4 + CAP * 8)
__global__ void __launch_bounds__(1024) k_front(const float* __restrict__ preds) {
    extern __shared__ char sm[];
    unsigned*           sh    = (unsigned*)sm;                  // hist -> bstart (in place)
    unsigned*           scur  = (unsigned*)(sm + NB * 4);       // write cursors
    unsigned long long* skeys = (unsigned long long*)(sm + 2 * NB * 4);
    __shared__ unsigned wsum[32];
    __shared__ int sb;

    const int img  = blockIdx.x;
    const int tid  = threadIdx.x;
    const int lane = tid & 31;
    const int wid  = tid >> 5;
    const float*  pimg  = preds + (size_t)img * NCH * NANCH;
    const float4* conf4 = (const float4*)(pimg + 4 * (size_t)NANCH);

    // ---- phase 1: histogram (smem atomics only) ----
    ((uint4*)sh)[tid] = make_uint4(0u, 0u, 0u, 0u);
    if (tid == 0) sb = 0;
    __syncthreads();
    for (int i = tid; i < NV4; i += 1024) {
        float4 v = conf4[i];
        if (v.x > CONF_T) atomicAdd(&sh[bucket_of(v.x)], 1u);
        if (v.y > CONF_T) atomicAdd(&sh[bucket_of(v.y)], 1u);
        if (v.z > CONF_T) atomicAdd(&sh[bucket_of(v.z)], 1u);
        if (v.w > CONF_T) atomicAdd(&sh[bucket_of(v.w)], 1u);
    }
    __syncthreads();

    // ---- phase 2: suffix scan -> bstart (in place) + cutoff ----
    uint4 hv = ((const uint4*)sh)[tid];
    unsigned tot = hv.x + hv.y + hv.z + hv.w;
    unsigned suf = tot;
    #pragma unroll
    for (int d = 1; d < 32; d <<= 1) {
        unsigned v = __shfl_down_sync(FULLM, suf, d);
        if (lane + d < 32) suf += v;
    }
    if (lane == 0) wsum[wid] = suf;
    __syncthreads();
    if (tid < 32) {
        unsigned v  = wsum[tid];
        unsigned sv = v;
        #pragma unroll
        for (int d = 1; d < 32; d <<= 1) {
            unsigned u = __shfl_down_sync(FULLM, sv, d);
            if (tid + d < 32) sv += u;
        }
        wsum[tid] = sv - v;
    }
    __syncthreads();
    unsigned run = wsum[wid] + (suf - tot);
    unsigned e3 = run;
    unsigned e2 = e3 + hv.w;
    unsigned e1 = e2 + hv.z;
    unsigned e0 = e1 + hv.y;
    uint4 ev = make_uint4(e0, e1, e2, e3);
    ((uint4*)sh)[tid]   = ev;   // bstart
    ((uint4*)scur)[tid] = ev;   // cursor init
    if      (e3 + hv.w >= (unsigned)KTOP) atomicMax(&sb, 4 * tid + 3);
    else if (e2 + hv.z >= (unsigned)KTOP) atomicMax(&sb, 4 * tid + 2);
    else if (e1 + hv.y >= (unsigned)KTOP) atomicMax(&sb, 4 * tid + 1);
    else if (e0 + hv.x >= (unsigned)KTOP) atomicMax(&sb, 4 * tid + 0);
    __syncthreads();
    const int cutoff = sb;

    // ---- phase 3: scatter into smem keys (conf re-read is L2-warm) ----
    for (int i = tid; i < NV4; i += 1024) {
        float4 v = conf4[i];
        float sv[4] = {v.x, v.y, v.z, v.w};
        int a = 4 * i;
        #pragma unroll
        for (int c = 0; c < 4; c++) {
            float s = sv[c];
            if (s > CONF_T) {
                int b = bucket_of(s);
                if (b >= cutoff) {
                    unsigned pos = atomicAdd(&scur[b], 1u);
                    if (pos < CAP)
                        skeys[pos] = ((unsigned long long)ordkey(s) << 16)
                                   | (unsigned)(65535 - (a + c));
                }
            }
        }
    }
    __syncthreads();

    // ---- phase 4: exact within-bucket rank -> g_keys2 sorted desc ----
    const int ntot = min((int)scur[cutoff], CAP);
    for (int p = tid; p < ntot; p += 1024) {
        unsigned long long key = skeys[p];
        float sc = inv_ordkey((unsigned)(key >> 16));
        int b   = bucket_of(sc);
        int st2 = (int)sh[b];
        int en2 = min((int)scur[b], CAP);
        int rank = st2;
        for (int q = st2; q < en2; q++) rank += (skeys[q] > key) ? 1 : 0;
        g_keys2[(size_t)img * CAP + rank] = key;
    }
    for (int p = ntot + tid; p < CAP; p += 1024)
        g_keys2[(size_t)img * CAP + p] = 0ull;
    if (tid == 0) g_ntot[img] = ntot;
}

// ================= K2: parallel 512x512 suppression matrix; last block resolves =================
// smem layout (bytes)
#define M_SBOX  0                        // 512*16 = 8192
#define M_SAREA 8192                     // 512*4  = 2048
#define M_SKEY  10240                    // 512*8  = 4096
#define M_SMAT  14336                    // 512*16*4 = 32768
#define M_LBOX  47104                    // 336*16 = 5376
#define M_LAREA 52480                    // 336*4  = 1344
#define M_LKEY  53824                    // 336*8  = 2688
#define M_TOTAL 56512

__global__ void __launch_bounds__(1024) k_matres(const float* __restrict__ preds) {
    extern __shared__ char sm[];
    float4*             sbox  = (float4*)(sm + M_SBOX);
    float*              sarea = (float*)(sm + M_SAREA);
    unsigned long long* skey  = (unsigned long long*)(sm + M_SKEY);
    unsigned*           smat  = (unsigned*)(sm + M_SMAT);
    float4*             lbox  = (float4*)(sm + M_LBOX);
    float*              slar  = (float*)(sm + M_LAREA);
    unsigned long long* lkey  = (unsigned long long*)(sm + M_LKEY);
    __shared__ unsigned sValid[NW], sSall[NW], sKept0[NW], sK0[NW], sKept[NW], sPref[NW];
    __shared__ int s_cur, slast;

    const int img  = blockIdx.x >> 3;
    const int part = blockIdx.x & 7;
    const int tid  = threadIdx.x;
    const int lane = tid & 31;
    const int w    = tid >> 5;
    const float* pimg = preds + (size_t)img * NCH * NANCH;
    const int ntot = g_ntot[img];

    // ---- decode top-512 candidates ----
    if (tid < NSEL) {
        unsigned long long key = g_keys2[(size_t)img * CAP + tid];
        skey[tid] = key;
        float4 b; float ar;
        decode_box(pimg, key, b, ar);
        sbox[tid] = b; sarea[tid] = ar;
    }
    __syncthreads();

    // ---- slab of upper-triangular suppression matrix ----
    {
        const int cw   = w & 15;          // column word
        const int half = w >> 4;          // row half
        const int j    = cw * 32 + lane;
        float4 bj = sbox[j];
        float  aj = sarea[j];
        const int i0 = part * 64 + half * 32;
        #pragma unroll 4
        for (int r = 0; r < 32; r++) {
            const int i = i0 + r;
            if (cw >= (i >> 5)) {
                float4 bi = sbox[i];
                float  ai = sarea[i];
                bool bit = (j > i) && sup_test(bi.x, bi.y, bi.z, bi.w, ai,
                                               bj.x, bj.y, bj.z, bj.w, aj);
                unsigned bm = __ballot_sync(FULLM, bit);
                if (lane == 0) g_mat[((size_t)img * NSEL + i) * NW + cw] = bm;
            }
        }
    }
    __syncthreads();
    if (tid == 0) {
        __threadfence();
        slast = (atomicAdd(&g_done3[img], 1u) == BPI - 1);
    }
    __syncthreads();
    if (!slast) return;

    // ---- last block: exact greedy resolve via bit algebra ----
    __threadfence();
    if (tid == 0) { g_done3[img] = 0u; s_cur = 0; }
    for (int idx = tid; idx < NSEL * NW; idx += 1024)
        smat[idx] = g_mat[(size_t)img * NSEL * NW + idx];
    __syncthreads();

    // valid masks
    if (w < NW) {
        int c = w * 32 + lane;
        bool valid = (c < ntot) && (skey[c] != 0ull);
        unsigned vb = __ballot_sync(FULLM, valid);
        if (lane == 0) sValid[w] = vb;
    }
    __syncthreads();
    // S_all[w] = OR of all valid rows' word w
    if (w < NW) {
        unsigned acc = 0;
        for (int k = 0; k <= w; k++) {
            int c = k * 32 + lane;
            if ((sValid[k] >> lane) & 1u) acc |= smat[c * NW + w];
        }
        acc = __reduce_or_sync(FULLM, acc);
        if (lane == 0) sSall[w] = acc;
    }
    __syncthreads();
    if (w < NW && lane == 0) sKept0[w] = sValid[w] & ~sSall[w];   // definitely kept
    __syncthreads();
    // S_k0[w] = OR of kept0 rows' word w
    if (w < NW) {
        unsigned acc = 0;
        for (int k = 0; k <= w; k++) {
            int c = k * 32 + lane;
            if ((sKept0[k] >> lane) & 1u) acc |= smat[c * NW + w];
        }
        acc = __reduce_or_sync(FULLM, acc);
        if (lane == 0) sK0[w] = acc;
    }
    __syncthreads();

    // warp 0: resolve contested candidates serially (bit lookups only) + prefix
    if (tid < 32) {
        unsigned Sck = 0;       // lane l<16 holds contested-kept OR, word l
        unsigned keptReg = 0;   // lane m holds kept mask word m
        for (int m = 0; m < NW; m++) {
            unsigned cont = sValid[m] & sSall[m];
            unsigned kc = 0;
            while (cont) {
                int bit = __ffs(cont) - 1;
                cont &= cont - 1u;
                int c = m * 32 + bit;
                unsigned sckm = __shfl_sync(FULLM, Sck, m);
                bool suppressed = (((sK0[m] | sckm) >> bit) & 1u) != 0u;
                if (!suppressed) {
                    kc |= 1u << bit;
                    if (lane < NW && lane >= m) Sck |= smat[c * NW + lane];
                }
            }
            unsigned kw = (sValid[m] & ~sSall[m]) | kc;
            if (lane == m) keptReg = kw;
        }
        int cntw = __popc((lane < NW) ? keptReg : 0u);
        int inc = cntw;
        #pragma unroll
        for (int d = 1; d < 32; d <<= 1) {
            int v = __shfl_up_sync(FULLM, inc, d);
            if (lane >= d) inc += v;
        }
        if (lane < NW) { sKept[lane] = keptReg; sPref[lane] = inc - cntw; }
        if (lane == 31) s_cur = inc;    // total kept among NSEL
    }
    __syncthreads();

    // build compact kept list (index order)
    if (tid < NSEL) {
        int wrd = tid >> 5;
        int l   = tid & 31;
        unsigned km = sKept[wrd];
        if ((km >> l) & 1u) {
            int rank = (int)sPref[wrd] + __popc(km & ((1u << l) - 1u));
            if (rank < LCAPE) {
                lbox[rank] = sbox[tid];
                slar[rank] = sarea[tid];
                lkey[rank] = skey[tid];
            }
        }
    }
    __syncthreads();

    // exact fallback: continue past NSEL if fewer than MAXDET kept (rare/never)
    if (tid < 32) {
        int curf = s_cur;
        int lim  = min(min(ntot, CAP), KTOP);
        if (curf < MAXDET && lim > NSEL) {
            for (int c = NSEL; c < lim && curf < MAXDET; c++) {
                unsigned long long key = g_keys2[(size_t)img * CAP + c];
                if (key == 0ull) continue;
                float4 bc; float ac;
                decode_box(pimg, key, bc, ac);
                bool sup = false;
                for (int l = lane; l < curf; l += 32) {
                    float4 bl = lbox[l];
                    sup |= sup_test(bl.x, bl.y, bl.z, bl.w, slar[l],
                                    bc.x, bc.y, bc.z, bc.w, ac);
                }
                if (!__any_sync(FULLM, sup)) {
                    if (lane == 0 && curf < LCAPE) {
                        lbox[curf] = bc; slar[curf] = ac; lkey[curf] = key;
                    }
                    __syncwarp();
                    curf++;
                }
            }
        }
        if (lane == 0) s_cur = curf;
    }
    __syncthreads();

    const int cnt = min(s_cur, MAXDET);
    if (tid < cnt) {
        unsigned long long key = lkey[tid];
        g_selbox  [img * MAXDET + tid] = lbox[tid];
        g_selscore[img * MAXDET + tid] = inv_ordkey((unsigned)(key >> 16));
        g_selanch [img * MAXDET + tid] = 65535 - (int)(key & 0xFFFFull);
    }
    if (tid == 0) g_cnt[img] = cnt;
}

// ================= K3: wide output writer =================
#define TOTOUT (BS * MAXDET * 56)
__global__ void __launch_bounds__(1024) k_out(const float* __restrict__ preds,
                                              float* __restrict__ out) {
    int s = blockIdx.x * 1024 + threadIdx.x;
    if (s >= TOTOUT) return;
    const int img = s / (MAXDET * 56);
    const int rem = s % (MAXDET * 56);
    const int r   = rem / 56;
    const int f   = rem % 56;
    const int cnt = g_cnt[img];

    float v = 0.0f;
    if (r < cnt) {
        if (f < 4) {
            float4 b = g_selbox[img * MAXDET + r];
            v = (f == 0) ? b.x : (f == 1) ? b.y : (f == 2) ? b.z : b.w;
        } else if (f == 4) {
            v = g_selscore[img * MAXDET + r];
        } else {
            int c = f - 5;
            int a = g_selanch[img * MAXDET + r];
            v = preds[(size_t)img * NCH * NANCH + (size_t)(5 + c) * NANCH + a];
            if (c < 2) v = fminf(fmaxf(v, 0.0f), IMGW);
        }
    }
    const int OSC = BS * MAXDET * 4;
    const int OKP = OSC + BS * MAXDET;
    if (f < 4)       out[(img * MAXDET + r) * 4 + f] = v;
    else if (f == 4) out[OSC + img * MAXDET + r] = v;
    else             out[OKP + (img * MAXDET + r) * 51 + (f - 5)] = v;
}

// ---------------- launch ----------------
extern "C" void kernel_launch(void* const* d_in, const int* in_sizes, int n_in,
                              void* d_out, int out_size) {
    const float* preds = (const float*)d_in[0];
    float* out = (float*)d_out;
    cudaFuncSetAttribute(k_front,  cudaFuncAttributeMaxDynamicSharedMemorySize, F_SMEM);
    cudaFuncSetAttribute(k_matres, cudaFuncAttributeMaxDynamicSharedMemorySize, M_TOTAL);
    k_front <<<BS, 1024, F_SMEM>>>(preds);
    k_matres<<<BS * BPI, 1024, M_TOTAL>>>(preds);
    k_out   <<<(TOTOUT + 1023) / 1024, 1024>>>(preds, out);
}